// round 11
// baseline (speedup 1.0000x reference)
#include <cuda_runtime.h>
#include <math.h>

#define Hh   64
#define Ww   192
#define HW   12288
#define Wp   194
#define Pp   12804      // (64+2)*(192+2)
#define CIN  256
#define COUT 128
#define NPB  96         // p-blocks in gemm grid.x (HW/128)
#define LEAK 0.01f
#define EPSV 1e-5f

// ---------------- scratch (device globals) ----------------------------------
__device__ float g_xpad[CIN * Pp];    // padded input, channel-major [C][Pp]
__device__ float g_Y[CIN * HW];       // gather output [C][HW]
__device__ float g_Z[COUT * HW];      // pre-BN linear outputs
__device__ float g_T[COUT * HW];      // depthwise outputs
__device__ float g_ps[COUT * NPB];    // partial sums per (channel, p-block)
__device__ float g_pq[COUT * NPB];    // partial sum-of-squares

#define FFMA2(d, a, b) asm("fma.rn.f32x2 %0, %1, %2, %0;" : "+l"(d) : "l"(a), "l"(b))

// ---------------- pad (channel-major) ----------------------------------------
__global__ void k_pad(const float* __restrict__ x) {
    int i = blockIdx.x * 256 + threadIdx.x;
    if (i >= CIN * Pp) return;
    int c = i / Pp, pp = i - c * Pp;
    int pr = pp / Wp, pc = pp - pr * Wp;
    float v = 0.f;
    if (pr >= 1 && pr <= Hh && pc >= 1 && pc <= Ww)
        v = x[c * HW + (pr - 1) * Ww + (pc - 1)];
    g_xpad[i] = v;
}

// ---------------- stage-1 deformable gather (R5 version) ---------------------
// grid (HW/128=96, CIN/8=32), block 128. Thread: 1 pixel, 8 channels.
__global__ __launch_bounds__(128) void k_gather(const float* __restrict__ xr,
                                                const float* __restrict__ ro) {
    __shared__ float sro[8][9];
    int tid = threadIdx.x;
    int cb = blockIdx.y * 8;
    if (tid < 72) sro[tid / 9][tid % 9] = ro[(cb + tid / 9) * 9 + tid % 9];
    __syncthreads();

    int p = blockIdx.x * 128 + tid;
    int r = p / Ww, q = p - r * Ww;
    float v = (float)((r + 1) * Wp + (q + 1));
    float o = 3.f / (1.f + expf(-xr[p]));
    const float PM1 = (float)(Pp - 1);

    if (blockIdx.x >= 3 && blockIdx.x <= 92) {
        // -------- fast path: rows 2..61 guaranteed, clamp provably inactive --
        int   base[6];
        float Wt[6][3];
#pragma unroll
        for (int t = 0; t < 6; t++) {
            int dy = (t >> 1) - 1;          // -1,0,1
            int sx = t & 1;                 // 0: xo=-1, 1: xo=+1
            float xo = sx ? 1.f : -1.f;
            float d  = (float)(dy * Wp);
            float pre   = v + xo + d;
            float offv  = __fadd_rn(__fmul_rn(o, xo), d);
            float after = pre + offv;
            float fo = floorf(offv), co = ceilf(offv);
            float avf  = pre + fo;
            float avf1 = avf + xo;
            float avc  = pre + co;
            float avc1 = avc + xo;
            float a1 = fabsf((after - avf)  / (float)Wp);
            float a2 = fabsf((avc1 - after) / (float)Wp);
            float w0 = a1 * fabsf(after - avf);
            float w1 = a1 * fabsf(avf1 - after);
            float w2 = a2 * fabsf(avc - after);
            float w3 = a2 * fabsf(after - avc1);
            bool ii = (co == fo);           // integer offset (rare)
            if (sx) {                       // xo=+1: positions i0, i0+1, i0+2
                base[t] = (int)avf;
                Wt[t][0] = w0 + (ii ? w2 : 0.f);
                Wt[t][1] = w1 + (ii ? w3 : w2);
                Wt[t][2] = ii ? 0.f : w3;
            } else {                        // xo=-1: positions i0-1, i0, i0+1
                base[t] = (int)avf - 1;
                Wt[t][0] = w1 + (ii ? w3 : 0.f);
                Wt[t][1] = w0 + (ii ? w2 : w3);
                Wt[t][2] = ii ? 0.f : w2;
            }
        }
#pragma unroll
        for (int j = 0; j < 8; j++) {
            const float* xp = g_xpad + (size_t)(cb + j) * Pp;
            float acc = 0.f;
#pragma unroll
            for (int t = 0; t < 6; t++) {
                int k = (t >> 1) * 3 + ((t & 1) ? 2 : 0);
                const float* bp = xp + base[t];
                float s = Wt[t][0] * __ldg(bp)
                        + Wt[t][1] * __ldg(bp + 1)
                        + Wt[t][2] * __ldg(bp + 2);
                acc += sro[j][k] * s;
            }
            g_Y[(size_t)(cb + j) * HW + p] = acc;
        }
    } else {
        // -------- generic path (edge rows) -----------------------------------
        int   idx[9][4];
        float wgt[9][4];
#pragma unroll
        for (int k = 0; k < 9; k++) {
            float xo = (float)(k % 3 - 1);
            float d  = (float)((k / 3 - 1) * Wp);
            float pre   = v + xo + d;
            float offv  = __fadd_rn(__fmul_rn(o, xo), d);
            float after = pre + offv;
            float fo = floorf(offv), co = ceilf(offv);
            float avf  = fminf(fmaxf(pre + fo, 0.f), PM1);
            float avf1 = fminf(fmaxf(avf + xo, 0.f), PM1);
            float avc  = fminf(fmaxf(pre + co, 0.f), PM1);
            float avc1 = fminf(fmaxf(avc + xo, 0.f), PM1);
            float a1 = fabsf((after - avf)  / (float)Wp);
            float a2 = fabsf((avc1 - after) / (float)Wp);
            wgt[k][0] = a1 * fabsf(after - avf);
            wgt[k][1] = a1 * fabsf(avf1 - after);
            wgt[k][2] = a2 * fabsf(avc - after);
            wgt[k][3] = a2 * fabsf(after - avc1);
            idx[k][0] = (int)avf;  idx[k][1] = (int)avf1;
            idx[k][2] = (int)avc;  idx[k][3] = (int)avc1;
        }
#pragma unroll
        for (int j = 0; j < 8; j++) {
            const float* xp = g_xpad + (size_t)(cb + j) * Pp;
            float acc = 0.f;
#pragma unroll
            for (int k = 0; k < 9; k++) {
                float s = wgt[k][0] * __ldg(xp + idx[k][0])
                        + wgt[k][1] * __ldg(xp + idx[k][1])
                        + wgt[k][2] * __ldg(xp + idx[k][2])
                        + wgt[k][3] * __ldg(xp + idx[k][3]);
                acc += sro[j][k] * s;
            }
            g_Y[(size_t)(cb + j) * HW + p] = acc;
        }
    }
}

// ---------------- f32x2 GEMM (NN): Z[o,p] = sum_k A[o,k]*B[k][p] ------------
// tile 32o x 128p, 128 threads, microtile 4o x 8p, FFMA2, global prefetch.
// grid (96, COUT/32). Epilogue: Z + per-(channel, p-block) partial sum/sumsq.
__global__ __launch_bounds__(128) void k_gemm(const float* __restrict__ A,
                                              const float* __restrict__ B,
                                              float* __restrict__ Z, int K) {
    __shared__ float2 As2[16][32];
    __shared__ float  Bs[16][128];
    int bx = blockIdx.x, by = blockIdx.y;
    int pbase = bx * 128, obase = by * 32;
    int tid = threadIdx.x;
    int og = tid >> 4, pg = tid & 15;
    unsigned long long acc[4][4] = {};

    int a_oo = tid >> 2, a_kq = (tid & 3) * 4;   // A: 32 rows x 16 k

    float4 a_nxt = *(const float4*)(A + (obase + a_oo) * K + a_kq);
    float4 b_nxt[4];
#pragma unroll
    for (int i = 0; i < 4; i++) {
        int idx = tid + i * 128;
        b_nxt[i] = *(const float4*)(B + (size_t)(idx >> 5) * HW + pbase + (idx & 31) * 4);
    }

    for (int kc = 0; kc < K; kc += 16) {
        As2[a_kq + 0][a_oo] = make_float2(a_nxt.x, a_nxt.x);
        As2[a_kq + 1][a_oo] = make_float2(a_nxt.y, a_nxt.y);
        As2[a_kq + 2][a_oo] = make_float2(a_nxt.z, a_nxt.z);
        As2[a_kq + 3][a_oo] = make_float2(a_nxt.w, a_nxt.w);
#pragma unroll
        for (int i = 0; i < 4; i++) {
            int idx = tid + i * 128;
            *(float4*)&Bs[idx >> 5][(idx & 31) * 4] = b_nxt[i];
        }
        __syncthreads();
        if (kc + 16 < K) {
            a_nxt = *(const float4*)(A + (obase + a_oo) * K + (kc + 16) + a_kq);
#pragma unroll
            for (int i = 0; i < 4; i++) {
                int idx = tid + i * 128;
                b_nxt[i] = *(const float4*)(B + (size_t)(kc + 16 + (idx >> 5)) * HW
                                            + pbase + (idx & 31) * 4);
            }
        }
#pragma unroll
        for (int kk = 0; kk < 16; kk++) {
            ulonglong2 b01 = *(const ulonglong2*)&Bs[kk][pg * 8];
            ulonglong2 b23 = *(const ulonglong2*)&Bs[kk][pg * 8 + 4];
            ulonglong2 a01 = *(const ulonglong2*)&As2[kk][og * 4];
            ulonglong2 a23 = *(const ulonglong2*)&As2[kk][og * 4 + 2];
            FFMA2(acc[0][0], a01.x, b01.x); FFMA2(acc[0][1], a01.x, b01.y);
            FFMA2(acc[0][2], a01.x, b23.x); FFMA2(acc[0][3], a01.x, b23.y);
            FFMA2(acc[1][0], a01.y, b01.x); FFMA2(acc[1][1], a01.y, b01.y);
            FFMA2(acc[1][2], a01.y, b23.x); FFMA2(acc[1][3], a01.y, b23.y);
            FFMA2(acc[2][0], a23.x, b01.x); FFMA2(acc[2][1], a23.x, b01.y);
            FFMA2(acc[2][2], a23.x, b23.x); FFMA2(acc[2][3], a23.x, b23.y);
            FFMA2(acc[3][0], a23.y, b01.x); FFMA2(acc[3][1], a23.y, b01.y);
            FFMA2(acc[3][2], a23.y, b23.x); FFMA2(acc[3][3], a23.y, b23.y);
        }
        __syncthreads();
    }

    float s[4], qq[4];
#pragma unroll
    for (int i = 0; i < 4; i++) {
        float2 v0 = *(float2*)&acc[i][0];
        float2 v1 = *(float2*)&acc[i][1];
        float2 v2 = *(float2*)&acc[i][2];
        float2 v3 = *(float2*)&acc[i][3];
        float* zp = Z + (size_t)(obase + og * 4 + i) * HW + pbase + pg * 8;
        *(float4*)(zp)     = make_float4(v0.x, v0.y, v1.x, v1.y);
        *(float4*)(zp + 4) = make_float4(v2.x, v2.y, v3.x, v3.y);
        s[i]  = ((v0.x + v0.y) + (v1.x + v1.y)) + ((v2.x + v2.y) + (v3.x + v3.y));
        qq[i] = ((v0.x * v0.x + v0.y * v0.y) + (v1.x * v1.x + v1.y * v1.y))
              + ((v2.x * v2.x + v2.y * v2.y) + (v3.x * v3.x + v3.y * v3.y));
    }
#pragma unroll
    for (int i = 0; i < 4; i++) {
#pragma unroll
        for (int w = 8; w; w >>= 1) {
            s[i]  += __shfl_down_sync(0xffffffff, s[i],  w, 16);
            qq[i] += __shfl_down_sync(0xffffffff, qq[i], w, 16);
        }
    }
    if (pg == 0) {
#pragma unroll
        for (int i = 0; i < 4; i++) {
            g_ps[(obase + og * 4 + i) * NPB + bx] = s[i];
            g_pq[(obase + og * 4 + i) * NPB + bx] = qq[i];
        }
    }
}

// ---------------- BN-stats prologue (per-block, redundant, hidden) -----------
__device__ __forceinline__ void bn_prologue(int c, const float* g, const float* b,
                                            float& sc, float& sh) {
    __shared__ float ss[256], sq[256];
    __shared__ float s_sc, s_sh;
    int t = threadIdx.x;
    float s = 0.f, qv = 0.f;
    if (t < NPB) { s = g_ps[c * NPB + t]; qv = g_pq[c * NPB + t]; }
    ss[t] = s; sq[t] = qv;
    __syncthreads();
    for (int st = 128; st; st >>= 1) {
        if (t < st) { ss[t] += ss[t + st]; sq[t] += sq[t + st]; }
        __syncthreads();
    }
    if (t == 0) {
        float mu  = ss[0] / (float)HW;
        float var = sq[0] / (float)HW - mu * mu;
        float rs  = rsqrtf(var + EPSV);
        float scv = g[c] * rs;
        s_sc = scv;
        s_sh = b[c] - mu * scv;
    }
    __syncthreads();
    sc = s_sc; sh = s_sh;
}

// ---------------- depthwise 3x3 on act(Z), fused BN stats --------------------
// grid (HW/256=48, COUT), block 256
__global__ __launch_bounds__(256) void k_dw(const float* __restrict__ Z,
                                            const float* __restrict__ dwz,
                                            float* __restrict__ T,
                                            const float* __restrict__ g,
                                            const float* __restrict__ b) {
    __shared__ float s_w[9];
    int c = blockIdx.y;
    if (threadIdx.x < 9) s_w[threadIdx.x] = dwz[c * 9 + threadIdx.x];
    float sc, sh;
    bn_prologue(c, g, b, sc, sh);   // includes __syncthreads (covers s_w)

    int p = blockIdx.x * 256 + threadIdx.x;
    int r = p / Ww, q = p - r * Ww;
    const float* z = Z + (size_t)c * HW;
    float acc = 0.f;
#pragma unroll
    for (int ky = 0; ky < 3; ky++) {
#pragma unroll
        for (int kx = 0; kx < 3; kx++) {
            int rr = r + ky - 1, qc = q + kx - 1;
            if (rr >= 0 && rr < Hh && qc >= 0 && qc < Ww) {
                float val = z[rr * Ww + qc] * sc + sh;
                val = (val >= 0.f) ? val : LEAK * val;
                acc += s_w[ky * 3 + kx] * val;
            }
        }
    }
    T[(size_t)c * HW + p] = acc;
}

// ---------------- final BN+leaky apply, fused BN stats -----------------------
// grid (HW/256=48, COUT), block 256
__global__ __launch_bounds__(256) void k_apply(const float* __restrict__ Z,
                                               float* __restrict__ out,
                                               const float* __restrict__ g,
                                               const float* __restrict__ b) {
    int c = blockIdx.y;
    float sc, sh;
    bn_prologue(c, g, b, sc, sh);
    int p = blockIdx.x * 256 + threadIdx.x;
    float v = Z[(size_t)c * HW + p] * sc + sh;
    out[(size_t)c * HW + p] = (v >= 0.f) ? v : LEAK * v;
}

// ---------------- launch ------------------------------------------------------
extern "C" void kernel_launch(void* const* d_in, const int* in_sizes, int n_in,
                              void* d_out, int out_size) {
    const float* x   = (const float*)d_in[0];
    const float* xr  = (const float*)d_in[1];
    const float* ro  = (const float*)d_in[2];
    const float* wr  = (const float*)d_in[3];
    const float* gr  = (const float*)d_in[4];
    const float* br  = (const float*)d_in[5];
    const float* dw1 = (const float*)d_in[6];
    const float* pw1 = (const float*)d_in[7];
    const float* g1  = (const float*)d_in[8];
    const float* b1  = (const float*)d_in[9];
    const float* dw2 = (const float*)d_in[10];
    const float* pw2 = (const float*)d_in[11];
    const float* g2  = (const float*)d_in[12];
    const float* b2  = (const float*)d_in[13];
    float* out = (float*)d_out;

    float *pY, *pZ, *pT;
    cudaGetSymbolAddress((void**)&pY, g_Y);
    cudaGetSymbolAddress((void**)&pZ, g_Z);
    cudaGetSymbolAddress((void**)&pT, g_T);

    k_pad<<<(CIN * Pp + 255) / 256, 256>>>(x);
    k_gather<<<dim3(HW / 128, CIN / 8), 128>>>(xr, ro);

    k_gemm<<<dim3(NPB, COUT / 32), 128>>>(wr, pY, pZ, CIN);
    k_dw<<<dim3(HW / 256, COUT), 256>>>(pZ, dw1, pT, gr, br);

    k_gemm<<<dim3(NPB, COUT / 32), 128>>>(pw1, pT, pZ, COUT);
    k_dw<<<dim3(HW / 256, COUT), 256>>>(pZ, dw2, pT, g1, b1);

    k_gemm<<<dim3(NPB, COUT / 32), 128>>>(pw2, pT, pZ, COUT);
    k_apply<<<dim3(HW / 256, COUT), 256>>>(pZ, out, g2, b2);
}

// round 12
// speedup vs baseline: 1.0382x; 1.0382x over previous
#include <cuda_runtime.h>
#include <math.h>

#define Hh   64
#define Ww   192
#define HW   12288
#define Wp   194
#define Pp   12804      // (64+2)*(192+2)
#define CIN  256
#define COUT 128
#define NPB  192        // p-blocks in gemm grid.x (HW/64)
#define LEAK 0.01f
#define EPSV 1e-5f

// ---------------- scratch (device globals) ----------------------------------
__device__ float g_xpad[CIN * Pp];    // padded input, channel-major [C][Pp]
__device__ float g_Y[CIN * HW];       // gather output [C][HW]
__device__ float g_Z[COUT * HW];      // pre-BN linear outputs
__device__ float g_T[COUT * HW];      // depthwise outputs
__device__ float g_ps[COUT * NPB];    // partial sums per (channel, p-block)
__device__ float g_pq[COUT * NPB];    // partial sum-of-squares

#define FFMA2(d, a, b) asm("fma.rn.f32x2 %0, %1, %2, %0;" : "+l"(d) : "l"(a), "l"(b))

// ---------------- pad (channel-major) ----------------------------------------
__global__ void k_pad(const float* __restrict__ x) {
    int i = blockIdx.x * 256 + threadIdx.x;
    if (i >= CIN * Pp) return;
    int c = i / Pp, pp = i - c * Pp;
    int pr = pp / Wp, pc = pp - pr * Wp;
    float v = 0.f;
    if (pr >= 1 && pr <= Hh && pc >= 1 && pc <= Ww)
        v = x[c * HW + (pr - 1) * Ww + (pc - 1)];
    g_xpad[i] = v;
}

// ---------------- stage-1 deformable gather (R5 version) ---------------------
// grid (HW/128=96, CIN/8=32), block 128. Thread: 1 pixel, 8 channels.
__global__ __launch_bounds__(128) void k_gather(const float* __restrict__ xr,
                                                const float* __restrict__ ro) {
    __shared__ float sro[8][9];
    int tid = threadIdx.x;
    int cb = blockIdx.y * 8;
    if (tid < 72) sro[tid / 9][tid % 9] = ro[(cb + tid / 9) * 9 + tid % 9];
    __syncthreads();

    int p = blockIdx.x * 128 + tid;
    int r = p / Ww, q = p - r * Ww;
    float v = (float)((r + 1) * Wp + (q + 1));
    float o = 3.f / (1.f + expf(-xr[p]));
    const float PM1 = (float)(Pp - 1);

    if (blockIdx.x >= 3 && blockIdx.x <= 92) {
        // -------- fast path: rows 2..61 guaranteed, clamp provably inactive --
        int   base[6];
        float Wt[6][3];
#pragma unroll
        for (int t = 0; t < 6; t++) {
            int dy = (t >> 1) - 1;          // -1,0,1
            int sx = t & 1;                 // 0: xo=-1, 1: xo=+1
            float xo = sx ? 1.f : -1.f;
            float d  = (float)(dy * Wp);
            float pre   = v + xo + d;
            float offv  = __fadd_rn(__fmul_rn(o, xo), d);
            float after = pre + offv;
            float fo = floorf(offv), co = ceilf(offv);
            float avf  = pre + fo;
            float avf1 = avf + xo;
            float avc  = pre + co;
            float avc1 = avc + xo;
            float a1 = fabsf((after - avf)  / (float)Wp);
            float a2 = fabsf((avc1 - after) / (float)Wp);
            float w0 = a1 * fabsf(after - avf);
            float w1 = a1 * fabsf(avf1 - after);
            float w2 = a2 * fabsf(avc - after);
            float w3 = a2 * fabsf(after - avc1);
            bool ii = (co == fo);           // integer offset (rare)
            if (sx) {                       // xo=+1: positions i0, i0+1, i0+2
                base[t] = (int)avf;
                Wt[t][0] = w0 + (ii ? w2 : 0.f);
                Wt[t][1] = w1 + (ii ? w3 : w2);
                Wt[t][2] = ii ? 0.f : w3;
            } else {                        // xo=-1: positions i0-1, i0, i0+1
                base[t] = (int)avf - 1;
                Wt[t][0] = w1 + (ii ? w3 : 0.f);
                Wt[t][1] = w0 + (ii ? w2 : w3);
                Wt[t][2] = ii ? 0.f : w2;
            }
        }
#pragma unroll
        for (int j = 0; j < 8; j++) {
            const float* xp = g_xpad + (size_t)(cb + j) * Pp;
            float acc = 0.f;
#pragma unroll
            for (int t = 0; t < 6; t++) {
                int k = (t >> 1) * 3 + ((t & 1) ? 2 : 0);
                const float* bp = xp + base[t];
                float s = Wt[t][0] * __ldg(bp)
                        + Wt[t][1] * __ldg(bp + 1)
                        + Wt[t][2] * __ldg(bp + 2);
                acc += sro[j][k] * s;
            }
            g_Y[(size_t)(cb + j) * HW + p] = acc;
        }
    } else {
        // -------- generic path (edge rows) -----------------------------------
        int   idx[9][4];
        float wgt[9][4];
#pragma unroll
        for (int k = 0; k < 9; k++) {
            float xo = (float)(k % 3 - 1);
            float d  = (float)((k / 3 - 1) * Wp);
            float pre   = v + xo + d;
            float offv  = __fadd_rn(__fmul_rn(o, xo), d);
            float after = pre + offv;
            float fo = floorf(offv), co = ceilf(offv);
            float avf  = fminf(fmaxf(pre + fo, 0.f), PM1);
            float avf1 = fminf(fmaxf(avf + xo, 0.f), PM1);
            float avc  = fminf(fmaxf(pre + co, 0.f), PM1);
            float avc1 = fminf(fmaxf(avc + xo, 0.f), PM1);
            float a1 = fabsf((after - avf)  / (float)Wp);
            float a2 = fabsf((avc1 - after) / (float)Wp);
            wgt[k][0] = a1 * fabsf(after - avf);
            wgt[k][1] = a1 * fabsf(avf1 - after);
            wgt[k][2] = a2 * fabsf(avc - after);
            wgt[k][3] = a2 * fabsf(after - avc1);
            idx[k][0] = (int)avf;  idx[k][1] = (int)avf1;
            idx[k][2] = (int)avc;  idx[k][3] = (int)avc1;
        }
#pragma unroll
        for (int j = 0; j < 8; j++) {
            const float* xp = g_xpad + (size_t)(cb + j) * Pp;
            float acc = 0.f;
#pragma unroll
            for (int k = 0; k < 9; k++) {
                float s = wgt[k][0] * __ldg(xp + idx[k][0])
                        + wgt[k][1] * __ldg(xp + idx[k][1])
                        + wgt[k][2] * __ldg(xp + idx[k][2])
                        + wgt[k][3] * __ldg(xp + idx[k][3]);
                acc += sro[j][k] * s;
            }
            g_Y[(size_t)(cb + j) * HW + p] = acc;
        }
    }
}

// ---------------- f32x2 GEMM (NN, R5 64x64): Z[o,p] = sum_k A[o,k]*B[k][p] --
// tile 64o x 64p, 128 threads, microtile 8o x 4p, FFMA2 inner loop.
// Epilogue: writes Z and per-(channel, p-block) partial sum / sumsq.
__global__ __launch_bounds__(128) void k_gemm(const float* __restrict__ A,
                                              const float* __restrict__ B,
                                              float* __restrict__ Z, int K) {
    __shared__ float2 As2[16][64];
    __shared__ float  Bs[16][64];
    int bx = blockIdx.x, by = blockIdx.y;
    int pbase = bx * 64, obase = by * 64;
    int tid = threadIdx.x;
    int og = tid >> 4, pg = tid & 15;
    unsigned long long acc[8][2] = {};

    for (int kc = 0; kc < K; kc += 16) {
#pragma unroll
        for (int i = 0; i < 2; i++) {
            int quad = tid + i * 128;
            int oo = quad >> 2, kq = (quad & 3) * 4;
            float4 a = *(const float4*)(A + (obase + oo) * K + kc + kq);
            As2[kq + 0][oo] = make_float2(a.x, a.x);
            As2[kq + 1][oo] = make_float2(a.y, a.y);
            As2[kq + 2][oo] = make_float2(a.z, a.z);
            As2[kq + 3][oo] = make_float2(a.w, a.w);
        }
#pragma unroll
        for (int i = 0; i < 2; i++) {
            int quad = tid + i * 128;
            int kk = quad >> 4, pq = (quad & 15) * 4;
            *(float4*)&Bs[kk][pq] =
                *(const float4*)(B + (size_t)(kc + kk) * HW + pbase + pq);
        }
        __syncthreads();
#pragma unroll
        for (int kk = 0; kk < 16; kk++) {
            ulonglong2 b2 = *(const ulonglong2*)&Bs[kk][pg * 4];
#pragma unroll
            for (int i2 = 0; i2 < 4; i2++) {
                ulonglong2 a2 = *(const ulonglong2*)&As2[kk][og * 8 + i2 * 2];
                FFMA2(acc[i2 * 2 + 0][0], a2.x, b2.x);
                FFMA2(acc[i2 * 2 + 0][1], a2.x, b2.y);
                FFMA2(acc[i2 * 2 + 1][0], a2.y, b2.x);
                FFMA2(acc[i2 * 2 + 1][1], a2.y, b2.y);
            }
        }
        __syncthreads();
    }

    float s[8], qq[8];
#pragma unroll
    for (int i = 0; i < 8; i++) {
        float2 lo = *(float2*)&acc[i][0];
        float2 hi = *(float2*)&acc[i][1];
        *(float4*)(Z + (size_t)(obase + og * 8 + i) * HW + pbase + pg * 4) =
            make_float4(lo.x, lo.y, hi.x, hi.y);
        s[i]  = lo.x + lo.y + hi.x + hi.y;
        qq[i] = lo.x * lo.x + lo.y * lo.y + hi.x * hi.x + hi.y * hi.y;
    }
#pragma unroll
    for (int i = 0; i < 8; i++) {
#pragma unroll
        for (int w = 8; w; w >>= 1) {
            s[i]  += __shfl_down_sync(0xffffffff, s[i],  w, 16);
            qq[i] += __shfl_down_sync(0xffffffff, qq[i], w, 16);
        }
    }
    if (pg == 0) {
#pragma unroll
        for (int i = 0; i < 8; i++) {
            g_ps[(obase + og * 8 + i) * NPB + bx] = s[i];
            g_pq[(obase + og * 8 + i) * NPB + bx] = qq[i];
        }
    }
}

// ---------------- BN-stats prologue (per-block, redundant, hidden) -----------
__device__ __forceinline__ void bn_prologue(int c, const float* g, const float* b,
                                            float& sc, float& sh) {
    __shared__ float ss[256], sq[256];
    __shared__ float s_sc, s_sh;
    int t = threadIdx.x;
    float s = 0.f, qv = 0.f;
    if (t < NPB) { s = g_ps[c * NPB + t]; qv = g_pq[c * NPB + t]; }
    ss[t] = s; sq[t] = qv;
    __syncthreads();
    for (int st = 128; st; st >>= 1) {
        if (t < st) { ss[t] += ss[t + st]; sq[t] += sq[t + st]; }
        __syncthreads();
    }
    if (t == 0) {
        float mu  = ss[0] / (float)HW;
        float var = sq[0] / (float)HW - mu * mu;
        float rs  = rsqrtf(var + EPSV);
        float scv = g[c] * rs;
        s_sc = scv;
        s_sh = b[c] - mu * scv;
    }
    __syncthreads();
    sc = s_sc; sh = s_sh;
}

// ---------------- depthwise 3x3 v2: smem row-halo, act pre-applied -----------
// grid (Hh=64, COUT=128), block 256. Block handles one (row, channel).
__global__ __launch_bounds__(256) void k_dw(const float* __restrict__ Z,
                                            const float* __restrict__ dwz,
                                            float* __restrict__ T,
                                            const float* __restrict__ g,
                                            const float* __restrict__ b) {
    __shared__ float sm[3][Wp];     // 3 halo rows, zero-padded cols
    __shared__ float s_w[9];
    int c = blockIdx.y, r = blockIdx.x;
    int tid = threadIdx.x;
    if (tid < 9) s_w[tid] = dwz[c * 9 + tid];
    float sc, sh;
    bn_prologue(c, g, b, sc, sh);   // trailing __syncthreads covers s_w

    const float* z = Z + (size_t)c * HW;
#pragma unroll
    for (int i = tid; i < 3 * Wp; i += 256) {
        int ky = i / Wp, col = i - ky * Wp;
        int rr = r + ky - 1, qc = col - 1;
        float val = 0.f;
        if (rr >= 0 && rr < Hh && qc >= 0 && qc < Ww) {
            float vv = z[rr * Ww + qc] * sc + sh;
            val = (vv >= 0.f) ? vv : LEAK * vv;
        }
        sm[ky][col] = val;
    }
    __syncthreads();

    if (tid < Ww) {
        float acc = 0.f;
#pragma unroll
        for (int ky = 0; ky < 3; ky++)
#pragma unroll
            for (int kx = 0; kx < 3; kx++)
                acc += s_w[ky * 3 + kx] * sm[ky][tid + kx];
        T[(size_t)c * HW + r * Ww + tid] = acc;
    }
}

// ---------------- final BN+leaky apply, fused BN stats -----------------------
// grid (HW/256=48, COUT), block 256
__global__ __launch_bounds__(256) void k_apply(const float* __restrict__ Z,
                                               float* __restrict__ out,
                                               const float* __restrict__ g,
                                               const float* __restrict__ b) {
    int c = blockIdx.y;
    float sc, sh;
    bn_prologue(c, g, b, sc, sh);
    int p = blockIdx.x * 256 + threadIdx.x;
    float v = Z[(size_t)c * HW + p] * sc + sh;
    out[(size_t)c * HW + p] = (v >= 0.f) ? v : LEAK * v;
}

// ---------------- launch ------------------------------------------------------
extern "C" void kernel_launch(void* const* d_in, const int* in_sizes, int n_in,
                              void* d_out, int out_size) {
    const float* x   = (const float*)d_in[0];
    const float* xr  = (const float*)d_in[1];
    const float* ro  = (const float*)d_in[2];
    const float* wr  = (const float*)d_in[3];
    const float* gr  = (const float*)d_in[4];
    const float* br  = (const float*)d_in[5];
    const float* dw1 = (const float*)d_in[6];
    const float* pw1 = (const float*)d_in[7];
    const float* g1  = (const float*)d_in[8];
    const float* b1  = (const float*)d_in[9];
    const float* dw2 = (const float*)d_in[10];
    const float* pw2 = (const float*)d_in[11];
    const float* g2  = (const float*)d_in[12];
    const float* b2  = (const float*)d_in[13];
    float* out = (float*)d_out;

    float *pY, *pZ, *pT;
    cudaGetSymbolAddress((void**)&pY, g_Y);
    cudaGetSymbolAddress((void**)&pZ, g_Z);
    cudaGetSymbolAddress((void**)&pT, g_T);

    k_pad<<<(CIN * Pp + 255) / 256, 256>>>(x);
    k_gather<<<dim3(HW / 128, CIN / 8), 128>>>(xr, ro);

    k_gemm<<<dim3(NPB, 2), 128>>>(wr, pY, pZ, CIN);
    k_dw<<<dim3(Hh, COUT), 256>>>(pZ, dw1, pT, gr, br);

    k_gemm<<<dim3(NPB, 2), 128>>>(pw1, pT, pZ, COUT);
    k_dw<<<dim3(Hh, COUT), 256>>>(pZ, dw2, pT, g1, b1);

    k_gemm<<<dim3(NPB, 2), 128>>>(pw2, pT, pZ, COUT);
    k_apply<<<dim3(HW / 256, COUT), 256>>>(pZ, out, g2, b2);
}

// round 13
// speedup vs baseline: 1.2994x; 1.2516x over previous
#include <cuda_runtime.h>
#include <math.h>

#define Hh   64
#define Ww   192
#define HW   12288
#define Wp   194
#define Pp   12804      // (64+2)*(192+2)
#define CIN  256
#define COUT 128
#define NPB  192        // p-blocks in gemm grid.x (HW/64)
#define LEAK 0.01f
#define EPSV 1e-5f

// ---------------- scratch (device globals) ----------------------------------
__device__ float g_xpad[CIN * Pp];    // padded input, channel-major [C][Pp]
__device__ float g_Y[CIN * HW];       // gather output [C][HW]
__device__ float g_Z[COUT * HW];      // pre-BN linear outputs
__device__ float g_T[COUT * HW];      // depthwise outputs
__device__ float g_ps[COUT * NPB];    // partial sums per (channel, p-block)
__device__ float g_pq[COUT * NPB];    // partial sum-of-squares

#define FFMA2(d, a, b) asm("fma.rn.f32x2 %0, %1, %2, %0;" : "+l"(d) : "l"(a), "l"(b))

// ---------------- pad (channel-major) ----------------------------------------
__global__ void k_pad(const float* __restrict__ x) {
    int i = blockIdx.x * 256 + threadIdx.x;
    if (i >= CIN * Pp) return;
    int c = i / Pp, pp = i - c * Pp;
    int pr = pp / Wp, pc = pp - pr * Wp;
    float v = 0.f;
    if (pr >= 1 && pr <= Hh && pc >= 1 && pc <= Ww)
        v = x[c * HW + (pr - 1) * Ww + (pc - 1)];
    g_xpad[i] = v;
}

// ---------------- stage-1 deformable gather (R5 version) ---------------------
// grid (HW/128=96, CIN/8=32), block 128. Thread: 1 pixel, 8 channels.
__global__ __launch_bounds__(128) void k_gather(const float* __restrict__ xr,
                                                const float* __restrict__ ro) {
    __shared__ float sro[8][9];
    int tid = threadIdx.x;
    int cb = blockIdx.y * 8;
    if (tid < 72) sro[tid / 9][tid % 9] = ro[(cb + tid / 9) * 9 + tid % 9];
    __syncthreads();

    int p = blockIdx.x * 128 + tid;
    int r = p / Ww, q = p - r * Ww;
    float v = (float)((r + 1) * Wp + (q + 1));
    float o = 3.f / (1.f + expf(-xr[p]));
    const float PM1 = (float)(Pp - 1);

    if (blockIdx.x >= 3 && blockIdx.x <= 92) {
        // -------- fast path: rows 2..61 guaranteed, clamp provably inactive --
        int   base[6];
        float Wt[6][3];
#pragma unroll
        for (int t = 0; t < 6; t++) {
            int dy = (t >> 1) - 1;          // -1,0,1
            int sx = t & 1;                 // 0: xo=-1, 1: xo=+1
            float xo = sx ? 1.f : -1.f;
            float d  = (float)(dy * Wp);
            float pre   = v + xo + d;
            float offv  = __fadd_rn(__fmul_rn(o, xo), d);
            float after = pre + offv;
            float fo = floorf(offv), co = ceilf(offv);
            float avf  = pre + fo;
            float avf1 = avf + xo;
            float avc  = pre + co;
            float avc1 = avc + xo;
            float a1 = fabsf((after - avf)  / (float)Wp);
            float a2 = fabsf((avc1 - after) / (float)Wp);
            float w0 = a1 * fabsf(after - avf);
            float w1 = a1 * fabsf(avf1 - after);
            float w2 = a2 * fabsf(avc - after);
            float w3 = a2 * fabsf(after - avc1);
            bool ii = (co == fo);           // integer offset (rare)
            if (sx) {                       // xo=+1: positions i0, i0+1, i0+2
                base[t] = (int)avf;
                Wt[t][0] = w0 + (ii ? w2 : 0.f);
                Wt[t][1] = w1 + (ii ? w3 : w2);
                Wt[t][2] = ii ? 0.f : w3;
            } else {                        // xo=-1: positions i0-1, i0, i0+1
                base[t] = (int)avf - 1;
                Wt[t][0] = w1 + (ii ? w3 : 0.f);
                Wt[t][1] = w0 + (ii ? w2 : w3);
                Wt[t][2] = ii ? 0.f : w2;
            }
        }
#pragma unroll
        for (int j = 0; j < 8; j++) {
            const float* xp = g_xpad + (size_t)(cb + j) * Pp;
            float acc = 0.f;
#pragma unroll
            for (int t = 0; t < 6; t++) {
                int k = (t >> 1) * 3 + ((t & 1) ? 2 : 0);
                const float* bp = xp + base[t];
                float s = Wt[t][0] * __ldg(bp)
                        + Wt[t][1] * __ldg(bp + 1)
                        + Wt[t][2] * __ldg(bp + 2);
                acc += sro[j][k] * s;
            }
            g_Y[(size_t)(cb + j) * HW + p] = acc;
        }
    } else {
        // -------- generic path (edge rows) -----------------------------------
        int   idx[9][4];
        float wgt[9][4];
#pragma unroll
        for (int k = 0; k < 9; k++) {
            float xo = (float)(k % 3 - 1);
            float d  = (float)((k / 3 - 1) * Wp);
            float pre   = v + xo + d;
            float offv  = __fadd_rn(__fmul_rn(o, xo), d);
            float after = pre + offv;
            float fo = floorf(offv), co = ceilf(offv);
            float avf  = fminf(fmaxf(pre + fo, 0.f), PM1);
            float avf1 = fminf(fmaxf(avf + xo, 0.f), PM1);
            float avc  = fminf(fmaxf(pre + co, 0.f), PM1);
            float avc1 = fminf(fmaxf(avc + xo, 0.f), PM1);
            float a1 = fabsf((after - avf)  / (float)Wp);
            float a2 = fabsf((avc1 - after) / (float)Wp);
            wgt[k][0] = a1 * fabsf(after - avf);
            wgt[k][1] = a1 * fabsf(avf1 - after);
            wgt[k][2] = a2 * fabsf(avc - after);
            wgt[k][3] = a2 * fabsf(after - avc1);
            idx[k][0] = (int)avf;  idx[k][1] = (int)avf1;
            idx[k][2] = (int)avc;  idx[k][3] = (int)avc1;
        }
#pragma unroll
        for (int j = 0; j < 8; j++) {
            const float* xp = g_xpad + (size_t)(cb + j) * Pp;
            float acc = 0.f;
#pragma unroll
            for (int k = 0; k < 9; k++) {
                float s = wgt[k][0] * __ldg(xp + idx[k][0])
                        + wgt[k][1] * __ldg(xp + idx[k][1])
                        + wgt[k][2] * __ldg(xp + idx[k][2])
                        + wgt[k][3] * __ldg(xp + idx[k][3]);
                acc += sro[j][k] * s;
            }
            g_Y[(size_t)(cb + j) * HW + p] = acc;
        }
    }
}

// ---------------- f32x2 GEMM (NN, R5 64x64): Z[o,p] = sum_k A[o,k]*B[k][p] --
__global__ __launch_bounds__(128) void k_gemm(const float* __restrict__ A,
                                              const float* __restrict__ B,
                                              float* __restrict__ Z, int K) {
    __shared__ float2 As2[16][64];
    __shared__ float  Bs[16][64];
    int bx = blockIdx.x, by = blockIdx.y;
    int pbase = bx * 64, obase = by * 64;
    int tid = threadIdx.x;
    int og = tid >> 4, pg = tid & 15;
    unsigned long long acc[8][2] = {};

    for (int kc = 0; kc < K; kc += 16) {
#pragma unroll
        for (int i = 0; i < 2; i++) {
            int quad = tid + i * 128;
            int oo = quad >> 2, kq = (quad & 3) * 4;
            float4 a = *(const float4*)(A + (obase + oo) * K + kc + kq);
            As2[kq + 0][oo] = make_float2(a.x, a.x);
            As2[kq + 1][oo] = make_float2(a.y, a.y);
            As2[kq + 2][oo] = make_float2(a.z, a.z);
            As2[kq + 3][oo] = make_float2(a.w, a.w);
        }
#pragma unroll
        for (int i = 0; i < 2; i++) {
            int quad = tid + i * 128;
            int kk = quad >> 4, pq = (quad & 15) * 4;
            *(float4*)&Bs[kk][pq] =
                *(const float4*)(B + (size_t)(kc + kk) * HW + pbase + pq);
        }
        __syncthreads();
#pragma unroll
        for (int kk = 0; kk < 16; kk++) {
            ulonglong2 b2 = *(const ulonglong2*)&Bs[kk][pg * 4];
#pragma unroll
            for (int i2 = 0; i2 < 4; i2++) {
                ulonglong2 a2 = *(const ulonglong2*)&As2[kk][og * 8 + i2 * 2];
                FFMA2(acc[i2 * 2 + 0][0], a2.x, b2.x);
                FFMA2(acc[i2 * 2 + 0][1], a2.x, b2.y);
                FFMA2(acc[i2 * 2 + 1][0], a2.y, b2.x);
                FFMA2(acc[i2 * 2 + 1][1], a2.y, b2.y);
            }
        }
        __syncthreads();
    }

    float s[8], qq[8];
#pragma unroll
    for (int i = 0; i < 8; i++) {
        float2 lo = *(float2*)&acc[i][0];
        float2 hi = *(float2*)&acc[i][1];
        *(float4*)(Z + (size_t)(obase + og * 8 + i) * HW + pbase + pg * 4) =
            make_float4(lo.x, lo.y, hi.x, hi.y);
        s[i]  = lo.x + lo.y + hi.x + hi.y;
        qq[i] = lo.x * lo.x + lo.y * lo.y + hi.x * hi.x + hi.y * hi.y;
    }
#pragma unroll
    for (int i = 0; i < 8; i++) {
#pragma unroll
        for (int w = 8; w; w >>= 1) {
            s[i]  += __shfl_down_sync(0xffffffff, s[i],  w, 16);
            qq[i] += __shfl_down_sync(0xffffffff, qq[i], w, 16);
        }
    }
    if (pg == 0) {
#pragma unroll
        for (int i = 0; i < 8; i++) {
            g_ps[(obase + og * 8 + i) * NPB + bx] = s[i];
            g_pq[(obase + og * 8 + i) * NPB + bx] = qq[i];
        }
    }
}

// ---------------- BN-stats prologue (per-block, amortized) -------------------
__device__ __forceinline__ void bn_prologue(int c, const float* g, const float* b,
                                            float& sc, float& sh) {
    __shared__ float ss[256], sq[256];
    __shared__ float s_sc, s_sh;
    int t = threadIdx.x;
    float s = 0.f, qv = 0.f;
    if (t < NPB) { s = g_ps[c * NPB + t]; qv = g_pq[c * NPB + t]; }
    ss[t] = s; sq[t] = qv;
    __syncthreads();
    for (int st = 128; st; st >>= 1) {
        if (t < st) { ss[t] += ss[t + st]; sq[t] += sq[t + st]; }
        __syncthreads();
    }
    if (t == 0) {
        float mu  = ss[0] / (float)HW;
        float var = sq[0] / (float)HW - mu * mu;
        float rs  = rsqrtf(var + EPSV);
        float scv = g[c] * rs;
        s_sc = scv;
        s_sh = b[c] - mu * scv;
    }
    __syncthreads();
    sc = s_sc; sh = s_sh;
}

// ---------------- depthwise 3x3 v3: 16-row strip per block -------------------
// grid (4, COUT) = 512 blocks, block 256. Each block: rows r0..r0+15 of one ch.
#define DWROWS 16
__global__ __launch_bounds__(256) void k_dw(const float* __restrict__ Z,
                                            const float* __restrict__ dwz,
                                            float* __restrict__ T,
                                            const float* __restrict__ g,
                                            const float* __restrict__ b) {
    __shared__ float sm[DWROWS + 2][Wp];   // halo strip, borders zeroed
    __shared__ float s_w[9];
    int c = blockIdx.y, r0 = blockIdx.x * DWROWS;
    int tid = threadIdx.x;
    if (tid < 9) s_w[tid] = dwz[c * 9 + tid];
    float sc, sh;
    bn_prologue(c, g, b, sc, sh);   // trailing __syncthreads covers s_w

    const float* z = Z + (size_t)c * HW;
    for (int i = tid; i < (DWROWS + 2) * Wp; i += 256) {
        int ky = i / Wp, col = i - ky * Wp;
        int rr = r0 + ky - 1, qc = col - 1;
        float val = 0.f;
        if (rr >= 0 && rr < Hh && qc >= 0 && qc < Ww) {
            float vv = z[rr * Ww + qc] * sc + sh;
            val = (vv >= 0.f) ? vv : LEAK * vv;
        }
        sm[ky][col] = val;
    }
    __syncthreads();

    float* tp = T + (size_t)c * HW + r0 * Ww;
#pragma unroll
    for (int i = 0; i < (DWROWS * Ww) / 256; i++) {
        int oi = i * 256 + tid;
        int orow = oi / Ww, ocol = oi - orow * Ww;
        float acc = 0.f;
#pragma unroll
        for (int ky = 0; ky < 3; ky++)
#pragma unroll
            for (int kx = 0; kx < 3; kx++)
                acc += s_w[ky * 3 + kx] * sm[orow + ky][ocol + kx];
        tp[oi] = acc;
    }
}

// ---------------- final BN+leaky apply, amortized prologue -------------------
// grid (8, COUT) = 1024 blocks, block 256, 6 pixels/thread
__global__ __launch_bounds__(256) void k_apply(const float* __restrict__ Z,
                                               float* __restrict__ out,
                                               const float* __restrict__ g,
                                               const float* __restrict__ b) {
    int c = blockIdx.y;
    float sc, sh;
    bn_prologue(c, g, b, sc, sh);
    const float* zp = Z + (size_t)c * HW + blockIdx.x * (HW / 8);
    float* op = out + (size_t)c * HW + blockIdx.x * (HW / 8);
#pragma unroll
    for (int i = 0; i < HW / 8 / 256; i++) {
        float v = zp[i * 256 + threadIdx.x] * sc + sh;
        op[i * 256 + threadIdx.x] = (v >= 0.f) ? v : LEAK * v;
    }
}

// ---------------- launch ------------------------------------------------------
extern "C" void kernel_launch(void* const* d_in, const int* in_sizes, int n_in,
                              void* d_out, int out_size) {
    const float* x   = (const float*)d_in[0];
    const float* xr  = (const float*)d_in[1];
    const float* ro  = (const float*)d_in[2];
    const float* wr  = (const float*)d_in[3];
    const float* gr  = (const float*)d_in[4];
    const float* br  = (const float*)d_in[5];
    const float* dw1 = (const float*)d_in[6];
    const float* pw1 = (const float*)d_in[7];
    const float* g1  = (const float*)d_in[8];
    const float* b1  = (const float*)d_in[9];
    const float* dw2 = (const float*)d_in[10];
    const float* pw2 = (const float*)d_in[11];
    const float* g2  = (const float*)d_in[12];
    const float* b2  = (const float*)d_in[13];
    float* out = (float*)d_out;

    float *pY, *pZ, *pT;
    cudaGetSymbolAddress((void**)&pY, g_Y);
    cudaGetSymbolAddress((void**)&pZ, g_Z);
    cudaGetSymbolAddress((void**)&pT, g_T);

    k_pad<<<(CIN * Pp + 255) / 256, 256>>>(x);
    k_gather<<<dim3(HW / 128, CIN / 8), 128>>>(xr, ro);

    k_gemm<<<dim3(NPB, 2), 128>>>(wr, pY, pZ, CIN);
    k_dw<<<dim3(Hh / DWROWS, COUT), 256>>>(pZ, dw1, pT, gr, br);

    k_gemm<<<dim3(NPB, 2), 128>>>(pw1, pT, pZ, COUT);
    k_dw<<<dim3(Hh / DWROWS, COUT), 256>>>(pZ, dw2, pT, g1, b1);

    k_gemm<<<dim3(NPB, 2), 128>>>(pw2, pT, pZ, COUT);
    k_apply<<<dim3(8, COUT), 256>>>(pZ, out, g2, b2);
}

// round 14
// speedup vs baseline: 1.3512x; 1.0399x over previous
#include <cuda_runtime.h>
#include <math.h>

#define Hh   64
#define Ww   192
#define HW   12288
#define Wp   194
#define Pp   12804      // (64+2)*(192+2)
#define CIN  256
#define COUT 128
#define NPB  192        // p-blocks in gemm grid.x (HW/64)
#define LEAK 0.01f
#define EPSV 1e-5f

// ---------------- scratch (device globals) ----------------------------------
__device__ float g_xpad[CIN * Pp];    // padded input, channel-major [C][Pp]
__device__ float g_Y[CIN * HW];       // gather output [C][HW]
__device__ float g_Z[COUT * HW];      // pre-BN linear outputs
__device__ float g_T[COUT * HW];      // depthwise outputs
__device__ float g_ps[COUT * NPB];    // partial sums per (channel, p-block)
__device__ float g_pq[COUT * NPB];    // partial sum-of-squares

#define FFMA2(d, a, b) asm("fma.rn.f32x2 %0, %1, %2, %0;" : "+l"(d) : "l"(a), "l"(b))

// ---------------- pad (channel-major) ----------------------------------------
__global__ void k_pad(const float* __restrict__ x) {
    int i = blockIdx.x * 256 + threadIdx.x;
    if (i >= CIN * Pp) return;
    int c = i / Pp, pp = i - c * Pp;
    int pr = pp / Wp, pc = pp - pr * Wp;
    float v = 0.f;
    if (pr >= 1 && pr <= Hh && pc >= 1 && pc <= Ww)
        v = x[c * HW + (pr - 1) * Ww + (pc - 1)];
    g_xpad[i] = v;
}

// ---------------- stage-1 deformable gather (R5 version) ---------------------
// grid (HW/128=96, CIN/8=32), block 128. Thread: 1 pixel, 8 channels.
__global__ __launch_bounds__(128) void k_gather(const float* __restrict__ xr,
                                                const float* __restrict__ ro) {
    __shared__ float sro[8][9];
    int tid = threadIdx.x;
    int cb = blockIdx.y * 8;
    if (tid < 72) sro[tid / 9][tid % 9] = ro[(cb + tid / 9) * 9 + tid % 9];
    __syncthreads();

    int p = blockIdx.x * 128 + tid;
    int r = p / Ww, q = p - r * Ww;
    float v = (float)((r + 1) * Wp + (q + 1));
    float o = 3.f / (1.f + expf(-xr[p]));
    const float PM1 = (float)(Pp - 1);

    if (blockIdx.x >= 3 && blockIdx.x <= 92) {
        // -------- fast path: rows 2..61 guaranteed, clamp provably inactive --
        int   base[6];
        float Wt[6][3];
#pragma unroll
        for (int t = 0; t < 6; t++) {
            int dy = (t >> 1) - 1;          // -1,0,1
            int sx = t & 1;                 // 0: xo=-1, 1: xo=+1
            float xo = sx ? 1.f : -1.f;
            float d  = (float)(dy * Wp);
            float pre   = v + xo + d;
            float offv  = __fadd_rn(__fmul_rn(o, xo), d);
            float after = pre + offv;
            float fo = floorf(offv), co = ceilf(offv);
            float avf  = pre + fo;
            float avf1 = avf + xo;
            float avc  = pre + co;
            float avc1 = avc + xo;
            float a1 = fabsf((after - avf)  / (float)Wp);
            float a2 = fabsf((avc1 - after) / (float)Wp);
            float w0 = a1 * fabsf(after - avf);
            float w1 = a1 * fabsf(avf1 - after);
            float w2 = a2 * fabsf(avc - after);
            float w3 = a2 * fabsf(after - avc1);
            bool ii = (co == fo);           // integer offset (rare)
            if (sx) {                       // xo=+1: positions i0, i0+1, i0+2
                base[t] = (int)avf;
                Wt[t][0] = w0 + (ii ? w2 : 0.f);
                Wt[t][1] = w1 + (ii ? w3 : w2);
                Wt[t][2] = ii ? 0.f : w3;
            } else {                        // xo=-1: positions i0-1, i0, i0+1
                base[t] = (int)avf - 1;
                Wt[t][0] = w1 + (ii ? w3 : 0.f);
                Wt[t][1] = w0 + (ii ? w2 : w3);
                Wt[t][2] = ii ? 0.f : w2;
            }
        }
#pragma unroll
        for (int j = 0; j < 8; j++) {
            const float* xp = g_xpad + (size_t)(cb + j) * Pp;
            float acc = 0.f;
#pragma unroll
            for (int t = 0; t < 6; t++) {
                int k = (t >> 1) * 3 + ((t & 1) ? 2 : 0);
                const float* bp = xp + base[t];
                float s = Wt[t][0] * __ldg(bp)
                        + Wt[t][1] * __ldg(bp + 1)
                        + Wt[t][2] * __ldg(bp + 2);
                acc += sro[j][k] * s;
            }
            g_Y[(size_t)(cb + j) * HW + p] = acc;
        }
    } else {
        // -------- generic path (edge rows) -----------------------------------
        int   idx[9][4];
        float wgt[9][4];
#pragma unroll
        for (int k = 0; k < 9; k++) {
            float xo = (float)(k % 3 - 1);
            float d  = (float)((k / 3 - 1) * Wp);
            float pre   = v + xo + d;
            float offv  = __fadd_rn(__fmul_rn(o, xo), d);
            float after = pre + offv;
            float fo = floorf(offv), co = ceilf(offv);
            float avf  = fminf(fmaxf(pre + fo, 0.f), PM1);
            float avf1 = fminf(fmaxf(avf + xo, 0.f), PM1);
            float avc  = fminf(fmaxf(pre + co, 0.f), PM1);
            float avc1 = fminf(fmaxf(avc + xo, 0.f), PM1);
            float a1 = fabsf((after - avf)  / (float)Wp);
            float a2 = fabsf((avc1 - after) / (float)Wp);
            wgt[k][0] = a1 * fabsf(after - avf);
            wgt[k][1] = a1 * fabsf(avf1 - after);
            wgt[k][2] = a2 * fabsf(avc - after);
            wgt[k][3] = a2 * fabsf(after - avc1);
            idx[k][0] = (int)avf;  idx[k][1] = (int)avf1;
            idx[k][2] = (int)avc;  idx[k][3] = (int)avc1;
        }
#pragma unroll
        for (int j = 0; j < 8; j++) {
            const float* xp = g_xpad + (size_t)(cb + j) * Pp;
            float acc = 0.f;
#pragma unroll
            for (int k = 0; k < 9; k++) {
                float s = wgt[k][0] * __ldg(xp + idx[k][0])
                        + wgt[k][1] * __ldg(xp + idx[k][1])
                        + wgt[k][2] * __ldg(xp + idx[k][2])
                        + wgt[k][3] * __ldg(xp + idx[k][3]);
                acc += sro[j][k] * s;
            }
            g_Y[(size_t)(cb + j) * HW + p] = acc;
        }
    }
}

// ---------------- f32x2 GEMM, double-buffered: Z[o,p]=sum_k A[o,k]B[k][p] ---
// tile 64o x 64p, 128 threads, microtile 8o x 4p, FFMA2, 1 sync per chunk.
__global__ __launch_bounds__(128) void k_gemm(const float* __restrict__ A,
                                              const float* __restrict__ B,
                                              float* __restrict__ Z, int K) {
    __shared__ float2 As2[2][16][64];
    __shared__ float  Bs[2][16][64];
    int bx = blockIdx.x, by = blockIdx.y;
    int pbase = bx * 64, obase = by * 64;
    int tid = threadIdx.x;
    int og = tid >> 4, pg = tid & 15;
    unsigned long long acc[8][2] = {};

    float4 aR[2], bR[2];
    // prolog: load chunk 0
#pragma unroll
    for (int i = 0; i < 2; i++) {
        int quad = tid + i * 128;
        aR[i] = *(const float4*)(A + (obase + (quad >> 2)) * K + (quad & 3) * 4);
        bR[i] = *(const float4*)(B + (size_t)(quad >> 4) * HW + pbase + (quad & 15) * 4);
    }
#pragma unroll
    for (int i = 0; i < 2; i++) {
        int quad = tid + i * 128;
        int oo = quad >> 2, kq = (quad & 3) * 4;
        As2[0][kq + 0][oo] = make_float2(aR[i].x, aR[i].x);
        As2[0][kq + 1][oo] = make_float2(aR[i].y, aR[i].y);
        As2[0][kq + 2][oo] = make_float2(aR[i].z, aR[i].z);
        As2[0][kq + 3][oo] = make_float2(aR[i].w, aR[i].w);
        *(float4*)&Bs[0][quad >> 4][(quad & 15) * 4] = bR[i];
    }
    __syncthreads();

    int nch = K >> 4;
    for (int ci = 0; ci < nch; ci++) {
        int cur = ci & 1;
        if (ci + 1 < nch) {
            int kc = (ci + 1) << 4;
#pragma unroll
            for (int i = 0; i < 2; i++) {
                int quad = tid + i * 128;
                aR[i] = *(const float4*)(A + (obase + (quad >> 2)) * K + kc + (quad & 3) * 4);
                bR[i] = *(const float4*)(B + (size_t)(kc + (quad >> 4)) * HW
                                         + pbase + (quad & 15) * 4);
            }
        }
#pragma unroll
        for (int kk = 0; kk < 16; kk++) {
            ulonglong2 b2 = *(const ulonglong2*)&Bs[cur][kk][pg * 4];
#pragma unroll
            for (int i2 = 0; i2 < 4; i2++) {
                ulonglong2 a2 = *(const ulonglong2*)&As2[cur][kk][og * 8 + i2 * 2];
                FFMA2(acc[i2 * 2 + 0][0], a2.x, b2.x);
                FFMA2(acc[i2 * 2 + 0][1], a2.x, b2.y);
                FFMA2(acc[i2 * 2 + 1][0], a2.y, b2.x);
                FFMA2(acc[i2 * 2 + 1][1], a2.y, b2.y);
            }
        }
        if (ci + 1 < nch) {
            int nb = cur ^ 1;
#pragma unroll
            for (int i = 0; i < 2; i++) {
                int quad = tid + i * 128;
                int oo = quad >> 2, kq = (quad & 3) * 4;
                As2[nb][kq + 0][oo] = make_float2(aR[i].x, aR[i].x);
                As2[nb][kq + 1][oo] = make_float2(aR[i].y, aR[i].y);
                As2[nb][kq + 2][oo] = make_float2(aR[i].z, aR[i].z);
                As2[nb][kq + 3][oo] = make_float2(aR[i].w, aR[i].w);
                *(float4*)&Bs[nb][quad >> 4][(quad & 15) * 4] = bR[i];
            }
        }
        __syncthreads();
    }

    float s[8], qq[8];
#pragma unroll
    for (int i = 0; i < 8; i++) {
        float2 lo = *(float2*)&acc[i][0];
        float2 hi = *(float2*)&acc[i][1];
        *(float4*)(Z + (size_t)(obase + og * 8 + i) * HW + pbase + pg * 4) =
            make_float4(lo.x, lo.y, hi.x, hi.y);
        s[i]  = lo.x + lo.y + hi.x + hi.y;
        qq[i] = lo.x * lo.x + lo.y * lo.y + hi.x * hi.x + hi.y * hi.y;
    }
#pragma unroll
    for (int i = 0; i < 8; i++) {
#pragma unroll
        for (int w = 8; w; w >>= 1) {
            s[i]  += __shfl_down_sync(0xffffffff, s[i],  w, 16);
            qq[i] += __shfl_down_sync(0xffffffff, qq[i], w, 16);
        }
    }
    if (pg == 0) {
#pragma unroll
        for (int i = 0; i < 8; i++) {
            g_ps[(obase + og * 8 + i) * NPB + bx] = s[i];
            g_pq[(obase + og * 8 + i) * NPB + bx] = qq[i];
        }
    }
}

// ---------------- BN-stats prologue (per-block, amortized) -------------------
__device__ __forceinline__ void bn_prologue(int c, const float* g, const float* b,
                                            float& sc, float& sh) {
    __shared__ float ss[256], sq[256];
    __shared__ float s_sc, s_sh;
    int t = threadIdx.x;
    float s = 0.f, qv = 0.f;
    if (t < NPB) { s = g_ps[c * NPB + t]; qv = g_pq[c * NPB + t]; }
    ss[t] = s; sq[t] = qv;
    __syncthreads();
    for (int st = 128; st; st >>= 1) {
        if (t < st) { ss[t] += ss[t + st]; sq[t] += sq[t + st]; }
        __syncthreads();
    }
    if (t == 0) {
        float mu  = ss[0] / (float)HW;
        float var = sq[0] / (float)HW - mu * mu;
        float rs  = rsqrtf(var + EPSV);
        float scv = g[c] * rs;
        s_sc = scv;
        s_sh = b[c] - mu * scv;
    }
    __syncthreads();
    sc = s_sc; sh = s_sh;
}

// ---------------- depthwise 3x3 v3.1: 16-row strip, div-free load ------------
// grid (4, COUT) = 512 blocks, block 256. Each block: rows r0..r0+15 of one ch.
#define DWROWS 16
__global__ __launch_bounds__(256) void k_dw(const float* __restrict__ Z,
                                            const float* __restrict__ dwz,
                                            float* __restrict__ T,
                                            const float* __restrict__ g,
                                            const float* __restrict__ b) {
    __shared__ float sm[DWROWS + 2][Wp];   // halo strip, borders zeroed
    __shared__ float s_w[9];
    int c = blockIdx.y, r0 = blockIdx.x * DWROWS;
    int tid = threadIdx.x;
    if (tid < 9) s_w[tid] = dwz[c * 9 + tid];
    float sc, sh;
    bn_prologue(c, g, b, sc, sh);   // trailing __syncthreads covers s_w

    const float* z = Z + (size_t)c * HW;
#pragma unroll
    for (int ky = 0; ky < DWROWS + 2; ky++) {
        int rr = r0 + ky - 1;
        bool rok = (rr >= 0) && (rr < Hh);
        for (int col = tid; col < Wp; col += 256) {
            int qc = col - 1;
            float val = 0.f;
            if (rok && qc >= 0 && qc < Ww) {
                float vv = z[rr * Ww + qc] * sc + sh;
                val = (vv >= 0.f) ? vv : LEAK * vv;
            }
            sm[ky][col] = val;
        }
    }
    __syncthreads();

    float* tp = T + (size_t)c * HW + r0 * Ww;
#pragma unroll
    for (int i = 0; i < (DWROWS * Ww) / 256; i++) {
        int oi = i * 256 + tid;
        int orow = oi / Ww, ocol = oi - orow * Ww;
        float acc = 0.f;
#pragma unroll
        for (int ky = 0; ky < 3; ky++)
#pragma unroll
            for (int kx = 0; kx < 3; kx++)
                acc += s_w[ky * 3 + kx] * sm[orow + ky][ocol + kx];
        tp[oi] = acc;
    }
}

// ---------------- final BN+leaky apply, amortized prologue -------------------
// grid (8, COUT) = 1024 blocks, block 256, 6 pixels/thread
__global__ __launch_bounds__(256) void k_apply(const float* __restrict__ Z,
                                               float* __restrict__ out,
                                               const float* __restrict__ g,
                                               const float* __restrict__ b) {
    int c = blockIdx.y;
    float sc, sh;
    bn_prologue(c, g, b, sc, sh);
    const float* zp = Z + (size_t)c * HW + blockIdx.x * (HW / 8);
    float* op = out + (size_t)c * HW + blockIdx.x * (HW / 8);
#pragma unroll
    for (int i = 0; i < HW / 8 / 256; i++) {
        float v = zp[i * 256 + threadIdx.x] * sc + sh;
        op[i * 256 + threadIdx.x] = (v >= 0.f) ? v : LEAK * v;
    }
}

// ---------------- launch ------------------------------------------------------
extern "C" void kernel_launch(void* const* d_in, const int* in_sizes, int n_in,
                              void* d_out, int out_size) {
    const float* x   = (const float*)d_in[0];
    const float* xr  = (const float*)d_in[1];
    const float* ro  = (const float*)d_in[2];
    const float* wr  = (const float*)d_in[3];
    const float* gr  = (const float*)d_in[4];
    const float* br  = (const float*)d_in[5];
    const float* dw1 = (const float*)d_in[6];
    const float* pw1 = (const float*)d_in[7];
    const float* g1  = (const float*)d_in[8];
    const float* b1  = (const float*)d_in[9];
    const float* dw2 = (const float*)d_in[10];
    const float* pw2 = (const float*)d_in[11];
    const float* g2  = (const float*)d_in[12];
    const float* b2  = (const float*)d_in[13];
    float* out = (float*)d_out;

    float *pY, *pZ, *pT;
    cudaGetSymbolAddress((void**)&pY, g_Y);
    cudaGetSymbolAddress((void**)&pZ, g_Z);
    cudaGetSymbolAddress((void**)&pT, g_T);

    k_pad<<<(CIN * Pp + 255) / 256, 256>>>(x);
    k_gather<<<dim3(HW / 128, CIN / 8), 128>>>(xr, ro);

    k_gemm<<<dim3(NPB, 2), 128>>>(wr, pY, pZ, CIN);
    k_dw<<<dim3(Hh / DWROWS, COUT), 256>>>(pZ, dw1, pT, gr, br);

    k_gemm<<<dim3(NPB, 2), 128>>>(pw1, pT, pZ, COUT);
    k_dw<<<dim3(Hh / DWROWS, COUT), 256>>>(pZ, dw2, pT, g1, b1);

    k_gemm<<<dim3(NPB, 2), 128>>>(pw2, pT, pZ, COUT);
    k_apply<<<dim3(8, COUT), 256>>>(pZ, out, g2, b2);
}